// round 3
// baseline (speedup 1.0000x reference)
#include <cuda_runtime.h>
#include <cstdint>
#include <cmath>

// ============================================================
// EncoderText: two-stage GRU + gumbel-softmax sampler (fp32)
// Shapes: B=128, T=128, D=300, E=1024, ASPACE=500, HEAD=2
// RNG: JAX threefry2x32, PARTITIONABLE mode (default >= 0.4.36)
// ============================================================

#define NB 128
#define NT 128
#define ND 300
#define NE 1024
#define NASP 500

// ---------------- static device scratch ----------------
__device__ float g_GI_cell[NB * NT * 900];     // x @ Wih_cell^T + bih   [b][t][900]
__device__ float g_GI_rnn[NB * NT * 3072];     // texts @ Wih_rnn^T + bih [t][b][3072]
__device__ float g_TEXTS[NT * NB * ND];        // [t][b][300]
__device__ float g_GH[NB * 900];
__device__ float g_MU[NB * 1000];
__device__ float g_CAT[NB * 600];
__device__ float g_HX[NB * ND];
__device__ float g_GH2[NB * 3072];
__device__ float g_HX2[NB * NE];
__device__ float g_LAST[NB * NE];

// ---------------- threefry2x32 core ----------------
__host__ __device__ __forceinline__ void tf2x32(uint32_t k0, uint32_t k1,
                                                uint32_t x0, uint32_t x1,
                                                uint32_t& o0, uint32_t& o1) {
    uint32_t ks2 = k0 ^ k1 ^ 0x1BD11BDAu;
    x0 += k0; x1 += k1;
#define TFR(r) { x0 += x1; x1 = (x1 << (r)) | (x1 >> (32 - (r))); x1 ^= x0; }
    TFR(13) TFR(15) TFR(26) TFR(6)   x0 += k1;  x1 += ks2 + 1u;
    TFR(17) TFR(29) TFR(16) TFR(24)  x0 += ks2; x1 += k0 + 2u;
    TFR(13) TFR(15) TFR(26) TFR(6)   x0 += k0;  x1 += k1 + 3u;
    TFR(17) TFR(29) TFR(16) TFR(24)  x0 += k1;  x1 += ks2 + 4u;
    TFR(13) TFR(15) TFR(26) TFR(6)   x0 += ks2; x1 += k0 + 5u;
#undef TFR
    o0 = x0; o1 = x1;
}

// Partitionable random_bits for 32-bit dtypes: element j -> o0 ^ o1 of
// threefry(key, hi=0, lo=j)   (total sizes here are < 2^32)
__device__ __forceinline__ uint32_t tf_bits_part(uint32_t k0, uint32_t k1, unsigned j) {
    uint32_t o0, o1;
    tf2x32(k0, k1, 0u, j, o0, o1);
    return o0 ^ o1;
}

__device__ __forceinline__ float tf_u01(uint32_t bits) {
    return __uint_as_float((bits >> 9) | 0x3f800000u) - 1.0f;
}

__device__ __forceinline__ float gumbelv(uint32_t k0, uint32_t k1, unsigned j) {
    float u = tf_u01(tf_bits_part(k0, k1, j));
    return -logf(-logf(u + 1e-20f) + 1e-20f);
}

// XLA ErfInv32 (Giles polynomial, w = -log1p(-x*x) to match XLA exactly)
__device__ __forceinline__ float erfinv_f(float x) {
    float w = -log1pf(-x * x);
    float p;
    if (w < 5.0f) {
        w -= 2.5f;
        p = 2.81022636e-08f;
        p = fmaf(p, w, 3.43273939e-07f);
        p = fmaf(p, w, -3.5233877e-06f);
        p = fmaf(p, w, -4.39150654e-06f);
        p = fmaf(p, w, 0.00021858087f);
        p = fmaf(p, w, -0.00125372503f);
        p = fmaf(p, w, -0.00417768164f);
        p = fmaf(p, w, 0.246640727f);
        p = fmaf(p, w, 1.50140941f);
    } else {
        w = sqrtf(w) - 3.0f;
        p = -0.000200214257f;
        p = fmaf(p, w, 0.000100950558f);
        p = fmaf(p, w, 0.00134934322f);
        p = fmaf(p, w, -0.00367342844f);
        p = fmaf(p, w, 0.00573950773f);
        p = fmaf(p, w, -0.0076224613f);
        p = fmaf(p, w, 0.00943887047f);
        p = fmaf(p, w, 1.00167406f);
        p = fmaf(p, w, 2.83297682f);
    }
    return p * x;
}

__device__ __forceinline__ float normalv(uint32_t k0, uint32_t k1, unsigned j) {
    float f = tf_u01(tf_bits_part(k0, k1, j));
    const float lo = -0.99999994f;          // nextafter(-1, 0) in f32
    float u = f * 2.0f + lo;                // (1 - lo) rounds to 2.0f in fp32
    u = fmaxf(lo, u);
    return 1.41421356237f * erfinv_f(u);    // np.float32(sqrt(2))
}

__device__ __forceinline__ float sigmoidf_(float x) {
    return 1.0f / (1.0f + expf(-x));
}

// ---------------- generic fp32 GEMM: C[M,N] = A[M,K] * W[N,K]^T + bias ----------------
template<int M, int N, int K, int BM, int BN, int BK, int TM, int TN>
__device__ __forceinline__ void gemm_core(const float* __restrict__ A,
                                          const float* __restrict__ W,
                                          const float* __restrict__ bias,
                                          float* __restrict__ C) {
    constexpr int THREADS = (BM / TM) * (BN / TN);
    __shared__ float As[BK][BM];
    __shared__ float Ws[BK][BN];
    const int tid  = threadIdx.x;
    const int tcol = tid % (BN / TN);
    const int trow = tid / (BN / TN);
    const int m0 = blockIdx.y * BM;
    const int n0 = blockIdx.x * BN;

    float acc[TM][TN];
#pragma unroll
    for (int i = 0; i < TM; i++)
#pragma unroll
        for (int j = 0; j < TN; j++) acc[i][j] = 0.0f;

    for (int k0 = 0; k0 < K; k0 += BK) {
#pragma unroll
        for (int idx = tid; idx < BM * BK; idx += THREADS) {
            int mm = idx / BK, kk = idx % BK;
            int gm = m0 + mm, gk = k0 + kk;
            As[kk][mm] = (gm < M && gk < K) ? A[(size_t)gm * K + gk] : 0.0f;
        }
#pragma unroll
        for (int idx = tid; idx < BN * BK; idx += THREADS) {
            int nn = idx / BK, kk = idx % BK;
            int gn = n0 + nn, gk = k0 + kk;
            Ws[kk][nn] = (gn < N && gk < K) ? W[(size_t)gn * K + gk] : 0.0f;
        }
        __syncthreads();
#pragma unroll
        for (int kk = 0; kk < BK; kk++) {
            float a[TM], w[TN];
#pragma unroll
            for (int i = 0; i < TM; i++) a[i] = As[kk][trow * TM + i];
#pragma unroll
            for (int j = 0; j < TN; j++) w[j] = Ws[kk][tcol * TN + j];
#pragma unroll
            for (int i = 0; i < TM; i++)
#pragma unroll
                for (int j = 0; j < TN; j++) acc[i][j] = fmaf(a[i], w[j], acc[i][j]);
        }
        __syncthreads();
    }

#pragma unroll
    for (int i = 0; i < TM; i++) {
        int gm = m0 + trow * TM + i;
        if (gm >= M) continue;
#pragma unroll
        for (int j = 0; j < TN; j++) {
            int gn = n0 + tcol * TN + j;
            if (gn >= N) continue;
            C[(size_t)gm * N + gn] = acc[i][j] + bias[gn];
        }
    }
}

__global__ __launch_bounds__(256) void k_gemm_gi_cell(const float* __restrict__ x,
                                                      const float* __restrict__ Wih,
                                                      const float* __restrict__ bih) {
    gemm_core<NB * NT, 900, 300, 64, 64, 16, 4, 4>(x, Wih, bih, g_GI_cell);
}
__global__ __launch_bounds__(256) void k_gemm_gh(const float* __restrict__ Whh,
                                                 const float* __restrict__ bhh) {
    gemm_core<NB, 900, 300, 32, 64, 16, 2, 4>(g_HX, Whh, bhh, g_GH);
}
__global__ __launch_bounds__(256) void k_gemm_mu(const float* __restrict__ Wmu,
                                                 const float* __restrict__ bmu) {
    gemm_core<NB, 1000, 600, 32, 64, 16, 2, 4>(g_CAT, Wmu, bmu, g_MU);
}
__global__ __launch_bounds__(256) void k_gemm_gi_rnn(const float* __restrict__ Wih,
                                                     const float* __restrict__ bih) {
    gemm_core<NB * NT, 3072, 300, 64, 64, 16, 4, 4>(g_TEXTS, Wih, bih, g_GI_rnn);
}
__global__ __launch_bounds__(256) void k_gemm_gh2(const float* __restrict__ Whh,
                                                  const float* __restrict__ bhh) {
    gemm_core<NB, 3072, 1024, 32, 64, 16, 2, 4>(g_HX2, Whh, bhh, g_GH2);
}

// ---------------- init: zero hidden states ----------------
__global__ void k_init() {
    int i = blockIdx.x * blockDim.x + threadIdx.x;
    if (i < NB * ND) g_HX[i] = 0.0f;
    if (i < NB * NE) g_HX2[i] = 0.0f;
}

// ---------------- stage-1 GRU combine + cat ----------------
__global__ void k_combine1(int t, const float* __restrict__ x) {
    int idx = blockIdx.x * blockDim.x + threadIdx.x;
    if (idx >= NB * ND) return;
    int b = idx / ND, d = idx % ND;
    size_t gib = ((size_t)b * NT + t) * 900;
    float gir = g_GI_cell[gib + d];
    float giz = g_GI_cell[gib + 300 + d];
    float gin = g_GI_cell[gib + 600 + d];
    float ghr = g_GH[b * 900 + d];
    float ghz = g_GH[b * 900 + 300 + d];
    float ghn = g_GH[b * 900 + 600 + d];
    float h = g_HX[idx];
    float r = sigmoidf_(gir + ghr);
    float z = sigmoidf_(giz + ghz);
    float n = tanhf(gin + r * ghn);
    float hn = (1.0f - z) * n + z * h;
    g_HX[idx] = hn;
    float img = x[((size_t)b * NT + t) * ND + d];
    g_CAT[b * 600 + d]       = fmaxf(img, 0.0f);
    g_CAT[b * 600 + 300 + d] = fmaxf(hn, 0.0f);
}

// ---------------- sampling: softmax + gumbel-max + text ----------------
__global__ void k_sample(int t, const float* __restrict__ x,
                         const float* __restrict__ Wlv, const float* __restrict__ blv,
                         float* __restrict__ out_slog, float* __restrict__ out_act,
                         float* __restrict__ out_logp,
                         uint2 nk0, uint2 nk1, uint2 nk2, uint2 nk3) {
    const int row = blockIdx.x;          // 0..255 = b*2 + h
    const int b = row >> 1, h = row & 1;
    const int tid = threadIdx.x;         // 128 threads

    __shared__ float ysh[NASP];
    __shared__ float red[32];
    __shared__ float redv[128];
    __shared__ int   redi[128];
    __shared__ float s_att;

    // ---- logvar: softplus(cat . Wlv[h] + blv[h]) ----
    float acc = 0.0f;
    for (int k = tid; k < 600; k += 128)
        acc += g_CAT[b * 600 + k] * Wlv[h * 600 + k];
#pragma unroll
    for (int o = 16; o; o >>= 1) acc += __shfl_xor_sync(0xffffffffu, acc, o);
    if ((tid & 31) == 0) red[tid >> 5] = acc;
    __syncthreads();
    float xlv = (red[0] + red[1] + red[2] + red[3]) + blv[h];
    float lv  = fmaxf(xlv, 0.0f) + log1pf(expf(-fabsf(xlv)));  // softplus
    float stdv = expf(0.5f * lv);
    __syncthreads();

    // ---- z = (mu + gumbel)/TEMP; block max ----
    const unsigned jbase = ((unsigned)t * 256u + (unsigned)row) * 500u;
    float zv[4];
    float m = -__int_as_float(0x7f800000);  // -inf
#pragma unroll
    for (int i = 0; i < 4; i++) {
        int a = tid + i * 128;
        if (a < NASP) {
            float mu = g_MU[b * 1000 + h * 500 + a];
            float g = gumbelv(nk0.x, nk0.y, jbase + a);
            zv[i] = (mu + g) / 0.8f;
            m = fmaxf(m, zv[i]);
        } else zv[i] = -__int_as_float(0x7f800000);
    }
#pragma unroll
    for (int o = 16; o; o >>= 1) m = fmaxf(m, __shfl_xor_sync(0xffffffffu, m, o));
    if ((tid & 31) == 0) red[tid >> 5] = m;
    __syncthreads();
    m = fmaxf(fmaxf(red[0], red[1]), fmaxf(red[2], red[3]));
    __syncthreads();

    // ---- sum of exp ----
    float ev[4];
    float ssum = 0.0f;
#pragma unroll
    for (int i = 0; i < 4; i++) {
        int a = tid + i * 128;
        if (a < NASP) { ev[i] = expf(zv[i] - m); ssum += ev[i]; }
        else ev[i] = 0.0f;
    }
#pragma unroll
    for (int o = 16; o; o >>= 1) ssum += __shfl_xor_sync(0xffffffffu, ssum, o);
    if ((tid & 31) == 0) red[tid >> 5] = ssum;
    __syncthreads();
    float S = red[0] + red[1] + red[2] + red[3];
    __syncthreads();

    // ---- y, score = log(y) + gc; local argmax ----
    float best = -__int_as_float(0x7f800000);
    int bidx = 0;
#pragma unroll
    for (int i = 0; i < 4; i++) {
        int a = tid + i * 128;
        if (a < NASP) {
            float yv = ev[i] / S;
            ysh[a] = yv;
            float sc = logf(yv) + gumbelv(nk1.x, nk1.y, jbase + a);
            if (sc > best) { best = sc; bidx = a; }
        }
    }
    redv[tid] = best; redi[tid] = bidx;
    __syncthreads();
    for (int s = 64; s > 0; s >>= 1) {
        if (tid < s) {
            float ov = redv[tid + s]; int oi = redi[tid + s];
            if (ov > redv[tid] || (ov == redv[tid] && oi < redi[tid])) {
                redv[tid] = ov; redi[tid] = oi;
            }
        }
        __syncthreads();
    }

    if (tid == 0) {
        int ind = redi[0];
        float yv = ysh[ind];
        float slog = logf(yv);
        float t2 = (1.0f - yv) + yv;                      // y_hard at ind (exact jax forward)
        float act = ((float)ind * t2) / 500.0f;
        unsigned je = ((unsigned)t * 128u + (unsigned)b) * 2u + (unsigned)h;
        float e1 = normalv(nk2.x, nk2.y, je);
        float e2 = normalv(nk3.x, nk3.y, je);
        float s1 = act + stdv * e1;
        float s2 = act + stdv * e2;
        float dd = (s2 - act) / stdv;
        float logp = -0.5f * dd * dd - logf(stdv) - 0.9189385332046727f;
        float attv = 20.0f * sigmoidf_(s1);
        out_slog[b * 256 + t * 2 + h]   = slog;  // [B,T,2] flat == [B,2,T] reshape view
        out_act[b * 256 + h * 128 + t]  = act;   // true transpose [B,2,T]
        out_logp[b * 256 + h * 128 + t] = logp;
        s_att = attv;
    }
    __syncthreads();
    float attv = s_att;
    for (int d2 = tid; d2 < 150; d2 += 128) {
        int dd = h * 150 + d2;
        g_TEXTS[((size_t)t * NB + b) * ND + dd] =
            x[((size_t)b * NT + t) * ND + dd] * attv;
    }
}

// ---------------- stage-2 GRU combine ----------------
__global__ void k_combine2(int t, const int* __restrict__ lengths) {
    int idx = blockIdx.x * blockDim.x + threadIdx.x;
    if (idx >= NB * NE) return;
    int b = idx / NE, e = idx % NE;
    size_t gib = ((size_t)t * NB + b) * 3072;
    float gir = g_GI_rnn[gib + e];
    float giz = g_GI_rnn[gib + 1024 + e];
    float gin = g_GI_rnn[gib + 2048 + e];
    float ghr = g_GH2[b * 3072 + e];
    float ghz = g_GH2[b * 3072 + 1024 + e];
    float ghn = g_GH2[b * 3072 + 2048 + e];
    float hp = g_HX2[idx];
    float r = sigmoidf_(gir + ghr);
    float z = sigmoidf_(giz + ghz);
    float n = tanhf(gin + r * ghn);
    float hn = (1.0f - z) * n + z * hp;
    g_HX2[idx] = hn;
    if (t == lengths[b] - 1) g_LAST[idx] = hn;
}

// ---------------- batchnorm (training stats) ----------------
__global__ void k_bn(const float* __restrict__ gamma, const float* __restrict__ beta,
                     float* __restrict__ out) {
    int e = blockIdx.x * 4 + (threadIdx.x >> 5);
    int lane = threadIdx.x & 31;
    float v[4];
    float s = 0.0f;
#pragma unroll
    for (int i = 0; i < 4; i++) { v[i] = g_LAST[(lane + i * 32) * NE + e]; s += v[i]; }
#pragma unroll
    for (int o = 16; o; o >>= 1) s += __shfl_xor_sync(0xffffffffu, s, o);
    float mean = s / 128.0f;
    float q = 0.0f;
#pragma unroll
    for (int i = 0; i < 4; i++) { float d = v[i] - mean; q += d * d; }
#pragma unroll
    for (int o = 16; o; o >>= 1) q += __shfl_xor_sync(0xffffffffu, q, o);
    float var = q / 128.0f;
    float denom = sqrtf(var + 1e-5f);
    float ga = gamma[e], be = beta[e];
#pragma unroll
    for (int i = 0; i < 4; i++)
        out[(lane + i * 32) * NE + e] = ga * (v[i] - mean) / denom + be;
}

// ---------------- host orchestration ----------------
extern "C" void kernel_launch(void* const* d_in, const int* in_sizes, int n_in,
                              void* d_out, int out_size) {
    const float* x        = (const float*)d_in[0];
    const int*   lengths  = (const int*)d_in[1];
    // d_in[2] = train (always 1)
    const float* Wih_cell = (const float*)d_in[3];
    const float* Whh_cell = (const float*)d_in[4];
    const float* bih_cell = (const float*)d_in[5];
    const float* bhh_cell = (const float*)d_in[6];
    const float* Wmu      = (const float*)d_in[7];
    const float* bmu      = (const float*)d_in[8];
    const float* Wlv      = (const float*)d_in[9];
    const float* blv      = (const float*)d_in[10];
    const float* Wih_rnn  = (const float*)d_in[11];
    const float* Whh_rnn  = (const float*)d_in[12];
    const float* bih_rnn  = (const float*)d_in[13];
    const float* bhh_rnn  = (const float*)d_in[14];
    const float* bn_gamma = (const float*)d_in[15];
    const float* bn_beta  = (const float*)d_in[16];

    float* out = (float*)d_out;
    float* out_feat = out;                       // [128,1024]
    float* out_slog = out + 131072;              // [128,2,128]
    float* out_act  = out + 131072 + 32768;      // [128,2,128]
    float* out_logp = out + 131072 + 65536;      // [128,2,128]

    // Partitionable (foldlike) split of key(42): child i = threefry(k, 0, i)
    uint2 nk[4];
    for (uint32_t i = 0; i < 4; i++) {
        uint32_t o0, o1;
        tf2x32(0u, 42u, 0u, i, o0, o1);
        nk[i] = make_uint2(o0, o1);
    }
    uint2 nk0 = nk[0];  // g_soft
    uint2 nk1 = nk[1];  // g_cat
    uint2 nk2 = nk[2];  // eps1
    uint2 nk3 = nk[3];  // eps2

    // Phase A: batched input projection for stage-1 GRU + zero hidden states
    k_init<<<(NB * NE + 255) / 256, 256>>>();
    k_gemm_gi_cell<<<dim3(15, 256), 256>>>(x, Wih_cell, bih_cell);

    // Phase B: stage-1 sequential scan
    for (int t = 0; t < NT; t++) {
        k_gemm_gh<<<dim3(15, 4), 256>>>(Whh_cell, bhh_cell);
        k_combine1<<<(NB * ND + 255) / 256, 256>>>(t, x);
        k_gemm_mu<<<dim3(16, 4), 256>>>(Wmu, bmu);
        k_sample<<<256, 128>>>(t, x, Wlv, blv, out_slog, out_act, out_logp,
                               nk0, nk1, nk2, nk3);
    }

    // Phase C: batched input projection for stage-2 GRU
    k_gemm_gi_rnn<<<dim3(48, 256), 256>>>(Wih_rnn, bih_rnn);

    // Phase D: stage-2 sequential scan
    for (int t = 0; t < NT; t++) {
        k_gemm_gh2<<<dim3(48, 4), 256>>>(Whh_rnn, bhh_rnn);
        k_combine2<<<(NB * NE + 255) / 256, 256>>>(t, lengths);
    }

    // Phase E: batchnorm on last hidden states
    k_bn<<<256, 128>>>(bn_gamma, bn_beta, out_feat);
}

// round 5
// speedup vs baseline: 1.2129x; 1.2129x over previous
#include <cuda_runtime.h>
#include <cstdint>
#include <cmath>

// ============================================================
// EncoderText: two-stage GRU + gumbel-softmax sampler (fp32)
// B=128, T=128, D=300, E=1024, ASPACE=500, HEAD=2
// RNG: JAX threefry2x32, partitionable mode
// ============================================================

#define NB 128
#define NT 128
#define ND 300
#define NE 1024
#define NASP 500

// ---------------- static device scratch ----------------
__device__ float g_GI_cell[NB * NT * 900];     // x @ Wih_cell^T + bih   [b][t][900]
__device__ float g_GI_rnn[NB * NT * 3072];     // texts @ Wih_rnn^T + bih [t][b][3072]
__device__ float g_TEXTS[NT * NB * ND];        // [t][b][300]
__device__ float g_MU[NB * 1000];
__device__ float g_CAT[NB * 600];
__device__ float g_HXa[NB * ND];
__device__ float g_HXb[NB * ND];
__device__ float g_H2a[NB * NE];
__device__ float g_H2b[NB * NE];
__device__ float g_LAST[NB * NE];

// ---------------- threefry2x32 core ----------------
__host__ __device__ __forceinline__ void tf2x32(uint32_t k0, uint32_t k1,
                                                uint32_t x0, uint32_t x1,
                                                uint32_t& o0, uint32_t& o1) {
    uint32_t ks2 = k0 ^ k1 ^ 0x1BD11BDAu;
    x0 += k0; x1 += k1;
#define TFR(r) { x0 += x1; x1 = (x1 << (r)) | (x1 >> (32 - (r))); x1 ^= x0; }
    TFR(13) TFR(15) TFR(26) TFR(6)   x0 += k1;  x1 += ks2 + 1u;
    TFR(17) TFR(29) TFR(16) TFR(24)  x0 += ks2; x1 += k0 + 2u;
    TFR(13) TFR(15) TFR(26) TFR(6)   x0 += k0;  x1 += k1 + 3u;
    TFR(17) TFR(29) TFR(16) TFR(24)  x0 += k1;  x1 += ks2 + 4u;
    TFR(13) TFR(15) TFR(26) TFR(6)   x0 += ks2; x1 += k0 + 5u;
#undef TFR
    o0 = x0; o1 = x1;
}

__device__ __forceinline__ uint32_t tf_bits_part(uint32_t k0, uint32_t k1, unsigned j) {
    uint32_t o0, o1;
    tf2x32(k0, k1, 0u, j, o0, o1);
    return o0 ^ o1;
}

__device__ __forceinline__ float tf_u01(uint32_t bits) {
    return __uint_as_float((bits >> 9) | 0x3f800000u) - 1.0f;
}

__device__ __forceinline__ float gumbelv(uint32_t k0, uint32_t k1, unsigned j) {
    float u = tf_u01(tf_bits_part(k0, k1, j));
    return -logf(-logf(u + 1e-20f) + 1e-20f);
}

// XLA ErfInv32 (Giles polynomial)
__device__ __forceinline__ float erfinv_f(float x) {
    float w = -log1pf(-x * x);
    float p;
    if (w < 5.0f) {
        w -= 2.5f;
        p = 2.81022636e-08f;
        p = fmaf(p, w, 3.43273939e-07f);
        p = fmaf(p, w, -3.5233877e-06f);
        p = fmaf(p, w, -4.39150654e-06f);
        p = fmaf(p, w, 0.00021858087f);
        p = fmaf(p, w, -0.00125372503f);
        p = fmaf(p, w, -0.00417768164f);
        p = fmaf(p, w, 0.246640727f);
        p = fmaf(p, w, 1.50140941f);
    } else {
        w = sqrtf(w) - 3.0f;
        p = -0.000200214257f;
        p = fmaf(p, w, 0.000100950558f);
        p = fmaf(p, w, 0.00134934322f);
        p = fmaf(p, w, -0.00367342844f);
        p = fmaf(p, w, 0.00573950773f);
        p = fmaf(p, w, -0.0076224613f);
        p = fmaf(p, w, 0.00943887047f);
        p = fmaf(p, w, 1.00167406f);
        p = fmaf(p, w, 2.83297682f);
    }
    return p * x;
}

__device__ __forceinline__ float normalv(uint32_t k0, uint32_t k1, unsigned j) {
    float f = tf_u01(tf_bits_part(k0, k1, j));
    const float lo = -0.99999994f;
    float u = f * 2.0f + lo;
    u = fmaxf(lo, u);
    return 1.41421356237f * erfinv_f(u);
}

__device__ __forceinline__ float sigmoidf_(float x) {
    return 1.0f / (1.0f + expf(-x));
}

// ---------------- generic fp32 GEMM: C[M,N] = A[M,K] * W[N,K]^T + bias ----------------
template<int M, int N, int K, int BM, int BN, int BK, int TM, int TN>
__device__ __forceinline__ void gemm_core(const float* __restrict__ A,
                                          const float* __restrict__ W,
                                          const float* __restrict__ bias,
                                          float* __restrict__ C) {
    constexpr int THREADS = (BM / TM) * (BN / TN);
    __shared__ float As[BK][BM];
    __shared__ float Ws[BK][BN];
    const int tid  = threadIdx.x;
    const int tcol = tid % (BN / TN);
    const int trow = tid / (BN / TN);
    const int m0 = blockIdx.y * BM;
    const int n0 = blockIdx.x * BN;

    float acc[TM][TN];
#pragma unroll
    for (int i = 0; i < TM; i++)
#pragma unroll
        for (int j = 0; j < TN; j++) acc[i][j] = 0.0f;

    for (int k0 = 0; k0 < K; k0 += BK) {
#pragma unroll
        for (int idx = tid; idx < BM * BK; idx += THREADS) {
            int mm = idx / BK, kk = idx % BK;
            int gm = m0 + mm, gk = k0 + kk;
            As[kk][mm] = (gm < M && gk < K) ? A[(size_t)gm * K + gk] : 0.0f;
        }
#pragma unroll
        for (int idx = tid; idx < BN * BK; idx += THREADS) {
            int nn = idx / BK, kk = idx % BK;
            int gn = n0 + nn, gk = k0 + kk;
            Ws[kk][nn] = (gn < N && gk < K) ? W[(size_t)gn * K + gk] : 0.0f;
        }
        __syncthreads();
#pragma unroll
        for (int kk = 0; kk < BK; kk++) {
            float a[TM], w[TN];
#pragma unroll
            for (int i = 0; i < TM; i++) a[i] = As[kk][trow * TM + i];
#pragma unroll
            for (int j = 0; j < TN; j++) w[j] = Ws[kk][tcol * TN + j];
#pragma unroll
            for (int i = 0; i < TM; i++)
#pragma unroll
                for (int j = 0; j < TN; j++) acc[i][j] = fmaf(a[i], w[j], acc[i][j]);
        }
        __syncthreads();
    }

#pragma unroll
    for (int i = 0; i < TM; i++) {
        int gm = m0 + trow * TM + i;
        if (gm >= M) continue;
#pragma unroll
        for (int j = 0; j < TN; j++) {
            int gn = n0 + tcol * TN + j;
            if (gn >= N) continue;
            C[(size_t)gm * N + gn] = acc[i][j] + bias[gn];
        }
    }
}

__global__ __launch_bounds__(256) void k_gemm_gi_cell(const float* __restrict__ x,
                                                      const float* __restrict__ Wih,
                                                      const float* __restrict__ bih) {
    gemm_core<NB * NT, 900, 300, 64, 64, 16, 4, 4>(x, Wih, bih, g_GI_cell);
}
__global__ __launch_bounds__(128) void k_gemm_mu(const float* __restrict__ Wmu,
                                                 const float* __restrict__ bmu) {
    gemm_core<NB, 1000, 600, 32, 32, 16, 2, 4>(g_CAT, Wmu, bmu, g_MU);
}
__global__ __launch_bounds__(256) void k_gemm_gi_rnn(const float* __restrict__ Wih,
                                                     const float* __restrict__ bih) {
    gemm_core<NB * NT, 3072, 300, 64, 64, 16, 4, 4>(g_TEXTS, Wih, bih, g_GI_rnn);
}

// ---------------- init: zero hidden states ----------------
__global__ void k_init() {
    int i = blockIdx.x * blockDim.x + threadIdx.x;
    if (i < NB * ND) g_HXa[i] = 0.0f;
    if (i < NB * NE) g_H2a[i] = 0.0f;
}

// ============================================================
// Fused stage-1 step: gh = h@Whh^T (3 gates) + GRU + relu-cat
// BM=16, BN=32 (over e<300), BK=20, 128 threads, TM=1, TN=4
// grid (10, 8)
// ============================================================
__global__ __launch_bounds__(128) void k_step1(int t, const float* __restrict__ x,
                                               const float* __restrict__ Whh,
                                               const float* __restrict__ bhh) {
    __shared__ __align__(16) float As[20][36];
    __shared__ __align__(16) float Ws[3][20][36];
    const int tid  = threadIdx.x;
    const int tcol = tid & 7;       // 8 col groups * TN=4
    const int trow = tid >> 3;      // 16 rows, TM=1
    const int n0 = blockIdx.x * 32;
    const int m0 = blockIdx.y * 16;
    const float* hsrc = (t & 1) ? g_HXb : g_HXa;
    float*       hdst = (t & 1) ? g_HXa : g_HXb;

    float acc[3][4] = {};

    for (int k0 = 0; k0 < 300; k0 += 20) {
        // A tile: 16 x 20
        for (int idx = tid; idx < 16 * 20; idx += 128) {
            int mm = idx / 20, kk = idx % 20;
            As[kk][mm] = hsrc[(m0 + mm) * 300 + k0 + kk];
        }
        // W tiles: 3 gates x 32 x 20
        for (int idx = tid; idx < 3 * 32 * 20; idx += 128) {
            int g = idx / 640, rem = idx % 640;
            int nn = rem / 20, kk = rem % 20;
            int gn = n0 + nn;
            Ws[g][kk][nn] = (gn < 300) ? Whh[(size_t)(g * 300 + gn) * 300 + k0 + kk] : 0.0f;
        }
        __syncthreads();
#pragma unroll
        for (int kk = 0; kk < 20; kk++) {
            float a = As[kk][trow];
#pragma unroll
            for (int g = 0; g < 3; g++) {
                float4 w = *(const float4*)&Ws[g][kk][tcol * 4];
                acc[g][0] = fmaf(a, w.x, acc[g][0]);
                acc[g][1] = fmaf(a, w.y, acc[g][1]);
                acc[g][2] = fmaf(a, w.z, acc[g][2]);
                acc[g][3] = fmaf(a, w.w, acc[g][3]);
            }
        }
        __syncthreads();
    }

    // epilogue: GRU gate math + CAT
    const int e = n0 + tcol * 4;
    if (e < 300) {
        const int b = m0 + trow;
        const float* gi = &g_GI_cell[((size_t)b * NT + t) * 900];
        float4 gr = *(const float4*)&gi[e];
        float4 gz = *(const float4*)&gi[300 + e];
        float4 gn4 = *(const float4*)&gi[600 + e];
        float4 h4 = *(const float4*)&hsrc[b * 300 + e];
        float4 xi = *(const float4*)&x[((size_t)b * NT + t) * 300 + e];
        float grx[4] = {gr.x, gr.y, gr.z, gr.w};
        float gzx[4] = {gz.x, gz.y, gz.z, gz.w};
        float gnx[4] = {gn4.x, gn4.y, gn4.z, gn4.w};
        float hx[4]  = {h4.x, h4.y, h4.z, h4.w};
        float xx[4]  = {xi.x, xi.y, xi.z, xi.w};
        float hn[4], ct[4];
#pragma unroll
        for (int j = 0; j < 4; j++) {
            float ghr = acc[0][j] + bhh[e + j];
            float ghz = acc[1][j] + bhh[300 + e + j];
            float ghn = acc[2][j] + bhh[600 + e + j];
            float r = sigmoidf_(grx[j] + ghr);
            float z = sigmoidf_(gzx[j] + ghz);
            float n = tanhf(gnx[j] + r * ghn);
            hn[j] = (1.0f - z) * n + z * hx[j];
            ct[j] = fmaxf(hn[j], 0.0f);
            xx[j] = fmaxf(xx[j], 0.0f);
        }
        *(float4*)&hdst[b * 300 + e] = make_float4(hn[0], hn[1], hn[2], hn[3]);
        *(float4*)&g_CAT[b * 600 + e] = make_float4(xx[0], xx[1], xx[2], xx[3]);
        *(float4*)&g_CAT[b * 600 + 300 + e] = make_float4(ct[0], ct[1], ct[2], ct[3]);
    }
}

// ============================================================
// Fused stage-2 step: gh2 = h@Whh_rnn^T (3 gates) + GRU
// BM=32, BN=32, BK=32, 128 threads, TM=2, TN=4, grid (32, 4)
// ============================================================
__global__ __launch_bounds__(128) void k_step2(int t, const int* __restrict__ lengths,
                                               const float* __restrict__ Whh,
                                               const float* __restrict__ bhh) {
    __shared__ __align__(16) float As[32][36];
    __shared__ __align__(16) float Ws[3][32][36];
    const int tid  = threadIdx.x;
    const int tcol = tid & 7;       // 8 col groups * TN=4
    const int trow = tid >> 3;      // 16 row groups * TM=2
    const int n0 = blockIdx.x * 32;
    const int m0 = blockIdx.y * 32;
    const float* hsrc = (t & 1) ? g_H2b : g_H2a;
    float*       hdst = (t & 1) ? g_H2a : g_H2b;

    float acc[3][2][4] = {};

    const int lr = tid >> 3;        // 16 load rows
    const int lk = (tid & 7) * 4;   // k offset (float4)

    for (int k0 = 0; k0 < 1024; k0 += 32) {
#pragma unroll
        for (int r = 0; r < 2; r++) {
            int mm = lr + r * 16;
            float4 v = *(const float4*)&hsrc[(m0 + mm) * 1024 + k0 + lk];
            As[lk + 0][mm] = v.x; As[lk + 1][mm] = v.y;
            As[lk + 2][mm] = v.z; As[lk + 3][mm] = v.w;
        }
#pragma unroll
        for (int g = 0; g < 3; g++) {
#pragma unroll
            for (int r = 0; r < 2; r++) {
                int nn = lr + r * 16;
                float4 v = *(const float4*)&Whh[(size_t)(g * 1024 + n0 + nn) * 1024 + k0 + lk];
                Ws[g][lk + 0][nn] = v.x; Ws[g][lk + 1][nn] = v.y;
                Ws[g][lk + 2][nn] = v.z; Ws[g][lk + 3][nn] = v.w;
            }
        }
        __syncthreads();
#pragma unroll
        for (int kk = 0; kk < 32; kk++) {
            float a0 = As[kk][trow * 2 + 0];
            float a1 = As[kk][trow * 2 + 1];
#pragma unroll
            for (int g = 0; g < 3; g++) {
                float4 w = *(const float4*)&Ws[g][kk][tcol * 4];
                acc[g][0][0] = fmaf(a0, w.x, acc[g][0][0]);
                acc[g][0][1] = fmaf(a0, w.y, acc[g][0][1]);
                acc[g][0][2] = fmaf(a0, w.z, acc[g][0][2]);
                acc[g][0][3] = fmaf(a0, w.w, acc[g][0][3]);
                acc[g][1][0] = fmaf(a1, w.x, acc[g][1][0]);
                acc[g][1][1] = fmaf(a1, w.y, acc[g][1][1]);
                acc[g][1][2] = fmaf(a1, w.z, acc[g][1][2]);
                acc[g][1][3] = fmaf(a1, w.w, acc[g][1][3]);
            }
        }
        __syncthreads();
    }

    // epilogue: GRU gate math, ping-pong write, LAST capture
    const int e = n0 + tcol * 4;
#pragma unroll
    for (int i = 0; i < 2; i++) {
        const int b = m0 + trow * 2 + i;
        const float* gi = &g_GI_rnn[((size_t)t * NB + b) * 3072];
        float4 gr = *(const float4*)&gi[e];
        float4 gz = *(const float4*)&gi[1024 + e];
        float4 gn4 = *(const float4*)&gi[2048 + e];
        float4 h4 = *(const float4*)&hsrc[b * 1024 + e];
        float grx[4] = {gr.x, gr.y, gr.z, gr.w};
        float gzx[4] = {gz.x, gz.y, gz.z, gz.w};
        float gnx[4] = {gn4.x, gn4.y, gn4.z, gn4.w};
        float hx[4]  = {h4.x, h4.y, h4.z, h4.w};
        float hn[4];
#pragma unroll
        for (int j = 0; j < 4; j++) {
            float ghr = acc[0][i][j] + bhh[e + j];
            float ghz = acc[1][i][j] + bhh[1024 + e + j];
            float ghn = acc[2][i][j] + bhh[2048 + e + j];
            float r = sigmoidf_(grx[j] + ghr);
            float z = sigmoidf_(gzx[j] + ghz);
            float n = tanhf(gnx[j] + r * ghn);
            hn[j] = (1.0f - z) * n + z * hx[j];
        }
        float4 o = make_float4(hn[0], hn[1], hn[2], hn[3]);
        *(float4*)&hdst[b * 1024 + e] = o;
        if (t == lengths[b] - 1) *(float4*)&g_LAST[b * 1024 + e] = o;
    }
}

// ---------------- sampling: softmax + gumbel-max + text ----------------
__global__ void k_sample(int t, const float* __restrict__ x,
                         const float* __restrict__ Wlv, const float* __restrict__ blv,
                         float* __restrict__ out_slog, float* __restrict__ out_act,
                         float* __restrict__ out_logp,
                         uint2 nk0, uint2 nk1, uint2 nk2, uint2 nk3) {
    const int row = blockIdx.x;          // 0..255 = b*2 + h
    const int b = row >> 1, h = row & 1;
    const int tid = threadIdx.x;         // 128 threads

    __shared__ float ysh[NASP];
    __shared__ float red[32];
    __shared__ float redv[128];
    __shared__ int   redi[128];
    __shared__ float s_att;

    // ---- logvar: softplus(cat . Wlv[h] + blv[h]) ----
    float acc = 0.0f;
    for (int k = tid; k < 600; k += 128)
        acc += g_CAT[b * 600 + k] * Wlv[h * 600 + k];
#pragma unroll
    for (int o = 16; o; o >>= 1) acc += __shfl_xor_sync(0xffffffffu, acc, o);
    if ((tid & 31) == 0) red[tid >> 5] = acc;
    __syncthreads();
    float xlv = (red[0] + red[1] + red[2] + red[3]) + blv[h];
    float lv  = fmaxf(xlv, 0.0f) + log1pf(expf(-fabsf(xlv)));
    float stdv = expf(0.5f * lv);
    __syncthreads();

    // ---- z = (mu + gumbel)/TEMP; block max ----
    const unsigned jbase = ((unsigned)t * 256u + (unsigned)row) * 500u;
    float zv[4];
    float m = -__int_as_float(0x7f800000);
#pragma unroll
    for (int i = 0; i < 4; i++) {
        int a = tid + i * 128;
        if (a < NASP) {
            float mu = g_MU[b * 1000 + h * 500 + a];
            float g = gumbelv(nk0.x, nk0.y, jbase + a);
            zv[i] = (mu + g) / 0.8f;
            m = fmaxf(m, zv[i]);
        } else zv[i] = -__int_as_float(0x7f800000);
    }
#pragma unroll
    for (int o = 16; o; o >>= 1) m = fmaxf(m, __shfl_xor_sync(0xffffffffu, m, o));
    if ((tid & 31) == 0) red[tid >> 5] = m;
    __syncthreads();
    m = fmaxf(fmaxf(red[0], red[1]), fmaxf(red[2], red[3]));
    __syncthreads();

    // ---- sum of exp ----
    float ev[4];
    float ssum = 0.0f;
#pragma unroll
    for (int i = 0; i < 4; i++) {
        int a = tid + i * 128;
        if (a < NASP) { ev[i] = expf(zv[i] - m); ssum += ev[i]; }
        else ev[i] = 0.0f;
    }
#pragma unroll
    for (int o = 16; o; o >>= 1) ssum += __shfl_xor_sync(0xffffffffu, ssum, o);
    if ((tid & 31) == 0) red[tid >> 5] = ssum;
    __syncthreads();
    float S = red[0] + red[1] + red[2] + red[3];
    __syncthreads();

    // ---- y, score = log(y) + gc; argmax ----
    float best = -__int_as_float(0x7f800000);
    int bidx = 0;
#pragma unroll
    for (int i = 0; i < 4; i++) {
        int a = tid + i * 128;
        if (a < NASP) {
            float yv = ev[i] / S;
            ysh[a] = yv;
            float sc = logf(yv) + gumbelv(nk1.x, nk1.y, jbase + a);
            if (sc > best) { best = sc; bidx = a; }
        }
    }
    redv[tid] = best; redi[tid] = bidx;
    __syncthreads();
    for (int s = 64; s > 0; s >>= 1) {
        if (tid < s) {
            float ov = redv[tid + s]; int oi = redi[tid + s];
            if (ov > redv[tid] || (ov == redv[tid] && oi < redi[tid])) {
                redv[tid] = ov; redi[tid] = oi;
            }
        }
        __syncthreads();
    }

    if (tid == 0) {
        int ind = redi[0];
        float yv = ysh[ind];
        float slog = logf(yv);
        float t2 = (1.0f - yv) + yv;
        float act = ((float)ind * t2) / 500.0f;
        unsigned je = ((unsigned)t * 128u + (unsigned)b) * 2u + (unsigned)h;
        float e1 = normalv(nk2.x, nk2.y, je);
        float e2 = normalv(nk3.x, nk3.y, je);
        float s1 = act + stdv * e1;
        float s2 = act + stdv * e2;
        float dd = (s2 - act) / stdv;
        float logp = -0.5f * dd * dd - logf(stdv) - 0.9189385332046727f;
        float attv = 20.0f * sigmoidf_(s1);
        out_slog[b * 256 + t * 2 + h]   = slog;
        out_act[b * 256 + h * 128 + t]  = act;
        out_logp[b * 256 + h * 128 + t] = logp;
        s_att = attv;
    }
    __syncthreads();
    float attv = s_att;
    for (int d2 = tid; d2 < 150; d2 += 128) {
        int dd = h * 150 + d2;
        g_TEXTS[((size_t)t * NB + b) * ND + dd] =
            x[((size_t)b * NT + t) * ND + dd] * attv;
    }
}

// ---------------- batchnorm (training stats) ----------------
__global__ void k_bn(const float* __restrict__ gamma, const float* __restrict__ beta,
                     float* __restrict__ out) {
    int e = blockIdx.x * 4 + (threadIdx.x >> 5);
    int lane = threadIdx.x & 31;
    float v[4];
    float s = 0.0f;
#pragma unroll
    for (int i = 0; i < 4; i++) { v[i] = g_LAST[(lane + i * 32) * NE + e]; s += v[i]; }
#pragma unroll
    for (int o = 16; o; o >>= 1) s += __shfl_xor_sync(0xffffffffu, s, o);
    float mean = s / 128.0f;
    float q = 0.0f;
#pragma unroll
    for (int i = 0; i < 4; i++) { float d = v[i] - mean; q += d * d; }
#pragma unroll
    for (int o = 16; o; o >>= 1) q += __shfl_xor_sync(0xffffffffu, q, o);
    float var = q / 128.0f;
    float denom = sqrtf(var + 1e-5f);
    float ga = gamma[e], be = beta[e];
#pragma unroll
    for (int i = 0; i < 4; i++)
        out[(lane + i * 32) * NE + e] = ga * (v[i] - mean) / denom + be;
}

// ---------------- host orchestration ----------------
extern "C" void kernel_launch(void* const* d_in, const int* in_sizes, int n_in,
                              void* d_out, int out_size) {
    const float* x        = (const float*)d_in[0];
    const int*   lengths  = (const int*)d_in[1];
    // d_in[2] = train (always 1)
    const float* Wih_cell = (const float*)d_in[3];
    const float* Whh_cell = (const float*)d_in[4];
    const float* bih_cell = (const float*)d_in[5];
    const float* bhh_cell = (const float*)d_in[6];
    const float* Wmu      = (const float*)d_in[7];
    const float* bmu      = (const float*)d_in[8];
    const float* Wlv      = (const float*)d_in[9];
    const float* blv      = (const float*)d_in[10];
    const float* Wih_rnn  = (const float*)d_in[11];
    const float* Whh_rnn  = (const float*)d_in[12];
    const float* bih_rnn  = (const float*)d_in[13];
    const float* bhh_rnn  = (const float*)d_in[14];
    const float* bn_gamma = (const float*)d_in[15];
    const float* bn_beta  = (const float*)d_in[16];

    float* out = (float*)d_out;
    float* out_feat = out;                       // [128,1024]
    float* out_slog = out + 131072;              // [128,2,128]
    float* out_act  = out + 131072 + 32768;      // [128,2,128]
    float* out_logp = out + 131072 + 65536;      // [128,2,128]

    // Partitionable split of key(42): child i = threefry(k, 0, i)
    uint2 nk[4];
    for (uint32_t i = 0; i < 4; i++) {
        uint32_t o0, o1;
        tf2x32(0u, 42u, 0u, i, o0, o1);
        nk[i] = make_uint2(o0, o1);
    }

    // Phase A: stage-1 batched input projection + zero hidden states
    k_init<<<(NB * NE + 255) / 256, 256>>>();
    k_gemm_gi_cell<<<dim3(15, 256), 256>>>(x, Wih_cell, bih_cell);

    // Phase B: stage-1 sequential scan (fused GRU step + mu GEMM + sampler)
    for (int t = 0; t < NT; t++) {
        k_step1<<<dim3(10, 8), 128>>>(t, x, Whh_cell, bhh_cell);
        k_gemm_mu<<<dim3(32, 4), 128>>>(Wmu, bmu);
        k_sample<<<256, 128>>>(t, x, Wlv, blv, out_slog, out_act, out_logp,
                               nk[0], nk[1], nk[2], nk[3]);
    }

    // Phase C: stage-2 batched input projection
    k_gemm_gi_rnn<<<dim3(48, 256), 256>>>(Wih_rnn, bih_rnn);

    // Phase D: stage-2 sequential scan (fused GEMM + GRU)
    for (int t = 0; t < NT; t++) {
        k_step2<<<dim3(32, 4), 128>>>(t, lengths, Whh_rnn, bhh_rnn);
    }

    // Phase E: batchnorm on last hidden states
    k_bn<<<256, 128>>>(bn_gamma, bn_beta, out_feat);
}